// round 15
// baseline (speedup 1.0000x reference)
#include <cuda_runtime.h>
#include <cuda_bf16.h>
#include <cstdint>

// ---------------------------------------------------------------------------
// GIN forward on GB300 — round 15
// R8 (reproduced 718.8us) + ONE change: BN finalize fused into GEMM1's TAIL
// via last-block-done counter (threadfence + atomic; 782nd block computes
// g_bna/g_bnb from g_stats). Removes 3 bn_finalize launches + boundaries.
// No streams/events (R14's leak + overlap direction abandoned).
// GEMM: D = Ahi@Bhi + Ahi@Blo + Alo@Bhi (Markidis), fp32 accum, mma.m16n8k16.
// ---------------------------------------------------------------------------

#define NN      50000
#define M_PAD   50048            // 391 * 128
#define HD      256
#define EMAX    800000
#define BN_EPS  1e-5f
#define GTILES  782              // 391 x 2 GEMM blocks per launch

// ------------------------- scratch (device globals) ------------------------
__device__ int   g_deg[NN];
__device__ int   g_cursor[NN];
__device__ int   g_rowptr[NN + 1];
__device__ int   g_adj[EMAX];
__device__ float g_m[(size_t)M_PAD * HD];       // aggregated (fp32)
__device__ float g_t[(size_t)M_PAD * HD];       // GEMM1 out (pre-BN)
__device__ float g_h[(size_t)M_PAD * HD];       // layer output
__device__ __nv_bfloat16 g_wthi[6 * HD * HD];   // weights [n,k] bf16 hi
__device__ __nv_bfloat16 g_wtlo[6 * HD * HD];   // bf16 lo
__device__ float g_stats[3 * 2 * HD];
__device__ int   g_bn_count[3];
__device__ __align__(16) float g_bna[HD];
__device__ __align__(16) float g_bnb[HD];

// ------------------------------ PTX helpers --------------------------------
__device__ __forceinline__ uint32_t smem_u32(const void* p) {
    uint32_t a;
    asm("{ .reg .u64 t; cvta.to.shared.u64 t, %1; cvt.u32.u64 %0, t; }"
        : "=r"(a) : "l"(p));
    return a;
}
#define CP_ASYNC16(dst, src) \
    asm volatile("cp.async.cg.shared.global [%0], [%1], 16;" \
                 :: "r"(dst), "l"(src) : "memory")
#define CP_COMMIT()  asm volatile("cp.async.commit_group;" ::: "memory")
#define CP_WAIT0()   asm volatile("cp.async.wait_group 0;" ::: "memory")
#define CP_WAIT1()   asm volatile("cp.async.wait_group 1;" ::: "memory")

__device__ __forceinline__ void ldm_x4(uint32_t* r, uint32_t addr) {
    asm volatile("ldmatrix.sync.aligned.m8n8.x4.shared.b16 {%0,%1,%2,%3}, [%4];"
                 : "=r"(r[0]), "=r"(r[1]), "=r"(r[2]), "=r"(r[3]) : "r"(addr));
}
__device__ __forceinline__ void mma_bf16(float* d, const uint32_t* a,
                                         const uint32_t* b) {
    asm volatile(
        "mma.sync.aligned.m16n8k16.row.col.f32.bf16.bf16.f32 "
        "{%0,%1,%2,%3}, {%4,%5,%6,%7}, {%8,%9}, {%0,%1,%2,%3};"
        : "+f"(d[0]), "+f"(d[1]), "+f"(d[2]), "+f"(d[3])
        : "r"(a[0]), "r"(a[1]), "r"(a[2]), "r"(a[3]), "r"(b[0]), "r"(b[1]));
}

// 64B-row swizzle: 16B unit u16 (0..3) XOR'd with ((row>>1)&3).
__device__ __forceinline__ uint32_t swz64(int row, int u16) {
    return (uint32_t)(row * 64 + (((u16) ^ ((row >> 1) & 3)) << 4));
}

// ------------------------------ zero init ----------------------------------
__global__ void zero_kernel() {
    int i = blockIdx.x * blockDim.x + threadIdx.x;
    if (i < NN) g_deg[i] = 0;
    if (i < 3 * 2 * HD) g_stats[i] = 0.f;
    if (i < 3) g_bn_count[i] = 0;
}

// ------------------------------ CSR build ----------------------------------
__global__ void hist_kernel(const int* __restrict__ ei, int E) {
    int i = blockIdx.x * blockDim.x + threadIdx.x;
    if (i < E) atomicAdd(&g_deg[ei[E + i]], 1);
}

__global__ void scan_kernel(int n) {
    __shared__ int wsum[32];
    __shared__ int carry;
    int tid = threadIdx.x, lane = tid & 31, wid = tid >> 5;
    if (tid == 0) carry = 0;
    __syncthreads();
    for (int base = 0; base < n; base += 1024) {
        int v = (base + tid < n) ? g_deg[base + tid] : 0;
        int x = v;
        #pragma unroll
        for (int off = 1; off < 32; off <<= 1) {
            int t = __shfl_up_sync(0xFFFFFFFFu, x, off);
            if (lane >= off) x += t;
        }
        if (lane == 31) wsum[wid] = x;
        __syncthreads();
        if (wid == 0) {
            int s = wsum[lane];
            #pragma unroll
            for (int off = 1; off < 32; off <<= 1) {
                int t = __shfl_up_sync(0xFFFFFFFFu, s, off);
                if (lane >= off) s += t;
            }
            wsum[lane] = s;
        }
        __syncthreads();
        int excl = carry + (wid ? wsum[wid - 1] : 0) + x - v;
        if (base + tid < n) {
            g_rowptr[base + tid] = excl;
            g_cursor[base + tid] = excl;
        }
        int total = wsum[31];
        __syncthreads();
        if (tid == 0) carry += total;
        __syncthreads();
    }
    if (tid == 0) g_rowptr[n] = carry;
}

__global__ void scatter_kernel(const int* __restrict__ ei, int E) {
    int i = blockIdx.x * blockDim.x + threadIdx.x;
    if (i < E) {
        int dst = ei[E + i];
        int pos = atomicAdd(&g_cursor[dst], 1);
        g_adj[pos] = ei[i];
    }
}

// --------------------------- pull aggregation ------------------------------
template <int K, bool FIRST>
__global__ void __launch_bounds__(256) agg_kernel(const float* __restrict__ hin) {
    constexpr int WPN = K / 128;
    constexpr int CV4 = K / 4;
    int gw   = (blockIdx.x * blockDim.x + threadIdx.x) >> 5;
    int lane = threadIdx.x & 31;
    int node = gw / WPN;
    int half = gw % WPN;
    if (node >= M_PAD) return;

    size_t vidx = (size_t)node * CV4 + half * 32 + lane;
    float4* m4 = reinterpret_cast<float4*>(g_m);

    if (node >= NN) {
        m4[vidx] = make_float4(0.f, 0.f, 0.f, 0.f);
        return;
    }

    const float*  h  = FIRST ? hin : (const float*)g_h;
    const float4* h4 = reinterpret_cast<const float4*>(h);
    const int co = half * 32 + lane;

    float4 acc = h4[vidx];

    int s = g_rowptr[node], e = g_rowptr[node + 1];
    int j = s;
    for (; j + 8 <= e; j += 8) {
        int idx[8];
        #pragma unroll
        for (int u = 0; u < 8; u++) idx[u] = __ldg(&g_adj[j + u]);
        float4 v[8];
        #pragma unroll
        for (int u = 0; u < 8; u++) v[u] = __ldg(&h4[(size_t)idx[u] * CV4 + co]);
        #pragma unroll
        for (int u = 0; u < 8; u++) {
            acc.x += v[u].x; acc.y += v[u].y; acc.z += v[u].z; acc.w += v[u].w;
        }
    }
    for (; j < e; j++) {
        int src = __ldg(&g_adj[j]);
        float4 v = __ldg(&h4[(size_t)src * CV4 + co]);
        acc.x += v.x; acc.y += v.y; acc.z += v.z; acc.w += v.w;
    }
    m4[vidx] = acc;
}

// --------------------------- weight prep -----------------------------------
__global__ void wprep_all_kernel(const float* __restrict__ w0,
                                 const float* __restrict__ w1,
                                 const float* __restrict__ w2,
                                 const float* __restrict__ w3,
                                 const float* __restrict__ w4,
                                 const float* __restrict__ w5) {
    int idx = blockIdx.x * blockDim.x + threadIdx.x;
    const int S0 = 128 * HD;
    const int TOTAL = S0 + 5 * HD * HD;
    if (idx >= TOTAL) return;
    const float* src;
    int slot, K, li;
    if (idx < S0) { slot = 0; K = 128; li = idx; src = w0; }
    else {
        int r = idx - S0;
        slot = 1 + r / (HD * HD);
        li = r % (HD * HD);
        K = 256;
        src = (slot == 1) ? w1 : (slot == 2) ? w2 : (slot == 3) ? w3
            : (slot == 4) ? w4 : w5;
    }
    int k = li / HD, n = li % HD;
    float v = src[li];
    __nv_bfloat16 hi = __float2bfloat16(v);
    float r2 = v - __bfloat162float(hi);
    size_t o = (size_t)slot * HD * HD + (size_t)n * K + k;
    g_wthi[o] = hi;
    g_wtlo[o] = __float2bfloat16(r2);
}

// -------------------------- mma.sync GEMM ----------------------------------
// R8 verbatim; P1 gains a last-block-done tail that computes g_bna/g_bnb.
#define AS32   16384
#define ATS    8192
#define BTS    8192
#define S_A32  0
#define S_AHI  32768
#define S_ALO  49152
#define S_BHI  65536
#define S_BLO  90112
#define S_TOT  114688

template <int K, bool P2>
__global__ void __launch_bounds__(256, 2) gemm_mma(
    int wslot, const float* __restrict__ bias, int Mreal, int layer,
    const float* __restrict__ gamma, const float* __restrict__ beta) {
    constexpr int CHUNKS = K / 32;
    extern __shared__ char smem[];
    const uint32_t sb = smem_u32(smem);

    const int tid  = threadIdx.x;
    const int wid  = tid >> 5;
    const int lane = tid & 31;
    const int rowBase = blockIdx.x * 128;
    const int colBase = blockIdx.y * 128;
    const int wm = (wid >> 1) * 32;
    const int wn = (wid & 1) * 64;

    const __nv_bfloat16* Whi = g_wthi + (size_t)wslot * HD * HD;
    const __nv_bfloat16* Wlo = g_wtlo + (size_t)wslot * HD * HD;
    const float* A = P2 ? (const float*)g_t : (const float*)g_m;
    float*       C = P2 ? g_h : g_t;

    auto prefetch = [&](int c) {
        const uint32_t as = (c & 1) * AS32;
        #pragma unroll
        for (int i = 0; i < 4; i++) {
            int u = tid + i * 256;
            int r = u >> 3, q = u & 7;
            CP_ASYNC16(sb + S_A32 + as + r * 128 + q * 16,
                       (const void*)&A[(size_t)(rowBase + r) * K + c * 32 + q * 4]);
        }
        const uint32_t bs = (c % 3) * BTS;
        #pragma unroll
        for (int i = 0; i < 2; i++) {
            int u = tid * 2 + i;
            int r = u >> 2, c8 = u & 3;
            uint32_t sof = bs + swz64(r, c8);
            size_t gb = (size_t)(colBase + r) * K + c * 32 + c8 * 8;
            CP_ASYNC16(sb + S_BHI + sof, (const void*)&Whi[gb]);
            CP_ASYNC16(sb + S_BLO + sof, (const void*)&Wlo[gb]);
        }
        CP_COMMIT();
    };

    auto transform = [&](int c) {
        const uint32_t as  = (c & 1) * AS32;
        const uint32_t ahs = (c & 1) * ATS;
        #pragma unroll
        for (int i = 0; i < 4; i++) {
            int u = tid + i * 256;
            int r = u >> 3, q = u & 7;
            float4 v = *reinterpret_cast<const float4*>(
                smem + S_A32 + as + r * 128 + q * 16);
            if (P2) {
                int col = c * 32 + q * 4;
                float4 a4 = *reinterpret_cast<const float4*>(&g_bna[col]);
                float4 b4 = *reinterpret_cast<const float4*>(&g_bnb[col]);
                v.x = fmaxf(fmaf(a4.x, v.x, b4.x), 0.f);
                v.y = fmaxf(fmaf(a4.y, v.y, b4.y), 0.f);
                v.z = fmaxf(fmaf(a4.z, v.z, b4.z), 0.f);
                v.w = fmaxf(fmaf(a4.w, v.w, b4.w), 0.f);
            }
            __nv_bfloat16 h0 = __float2bfloat16(v.x);
            __nv_bfloat16 h1 = __float2bfloat16(v.y);
            __nv_bfloat16 h2 = __float2bfloat16(v.z);
            __nv_bfloat16 h3 = __float2bfloat16(v.w);
            __nv_bfloat162 ph0 = __halves2bfloat162(h0, h1);
            __nv_bfloat162 ph1 = __halves2bfloat162(h2, h3);
            __nv_bfloat162 pl0 = __halves2bfloat162(
                __float2bfloat16(v.x - __bfloat162float(h0)),
                __float2bfloat16(v.y - __bfloat162float(h1)));
            __nv_bfloat162 pl1 = __halves2bfloat162(
                __float2bfloat16(v.z - __bfloat162float(h2)),
                __float2bfloat16(v.w - __bfloat162float(h3)));
            uint2 uh, ul;
            uh.x = *reinterpret_cast<uint32_t*>(&ph0);
            uh.y = *reinterpret_cast<uint32_t*>(&ph1);
            ul.x = *reinterpret_cast<uint32_t*>(&pl0);
            ul.y = *reinterpret_cast<uint32_t*>(&pl1);
            uint32_t off = ahs + swz64(r, q >> 1) + (q & 1) * 8;
            *reinterpret_cast<uint2*>(smem + S_AHI + off) = uh;
            *reinterpret_cast<uint2*>(smem + S_ALO + off) = ul;
        }
    };

    float acc[2][8][4];
    #pragma unroll
    for (int mt = 0; mt < 2; mt++)
        #pragma unroll
        for (int nt = 0; nt < 8; nt++)
            #pragma unroll
            for (int j = 0; j < 4; j++) acc[mt][nt][j] = 0.f;

    const int arow = (lane & 7) + ((lane >> 3) & 1) * 8;
    const int akh  = (lane >> 4) * 8;
    const int brow = (lane & 7) + ((lane >> 4) & 1) * 8;
    const int bkh  = ((lane >> 3) & 1) * 8;

    prefetch(0);
    prefetch(1);
    CP_WAIT1();
    transform(0);
    __syncthreads();

    #pragma unroll 1
    for (int c = 0; c < CHUNKS; c++) {
        if (c + 2 < CHUNKS) prefetch(c + 2);

        const uint32_t ahs = (c & 1) * ATS;
        const uint32_t bss = (c % 3) * BTS;
        #pragma unroll
        for (int kk = 0; kk < 32; kk += 16) {
            const int u16a = (kk + akh) >> 3;
            uint32_t ah[2][4], al[2][4];
            #pragma unroll
            for (int mt = 0; mt < 2; mt++) {
                uint32_t sw = swz64(wm + mt * 16 + arow, u16a);
                ldm_x4(ah[mt], sb + S_AHI + ahs + sw);
                ldm_x4(al[mt], sb + S_ALO + ahs + sw);
            }
            const int u16b = (kk + bkh) >> 3;
            #pragma unroll
            for (int np = 0; np < 4; np++) {
                uint32_t sw = swz64(wn + np * 16 + brow, u16b);
                uint32_t th[4], tl[4];
                ldm_x4(th, sb + S_BHI + bss + sw);
                ldm_x4(tl, sb + S_BLO + bss + sw);
                #pragma unroll
                for (int mt = 0; mt < 2; mt++) {
                    mma_bf16(acc[mt][np * 2],     ah[mt], th);
                    mma_bf16(acc[mt][np * 2],     ah[mt], tl);
                    mma_bf16(acc[mt][np * 2],     al[mt], th);
                    mma_bf16(acc[mt][np * 2 + 1], ah[mt], th + 2);
                    mma_bf16(acc[mt][np * 2 + 1], ah[mt], tl + 2);
                    mma_bf16(acc[mt][np * 2 + 1], al[mt], th + 2);
                }
            }
        }

        if (c + 1 < CHUNKS) {
            if (c + 2 < CHUNKS) { CP_WAIT1(); } else { CP_WAIT0(); }
            transform(c + 1);
        }
        __syncthreads();
    }

    // -------- epilogue --------
    const int erow  = rowBase + wm + (lane >> 2);
    const int ecol0 = colBase + wn + (lane & 3) * 2;

    float cs[8][2], cq[8][2];
    if (!P2) {
        #pragma unroll
        for (int nt = 0; nt < 8; nt++)
            cs[nt][0] = cs[nt][1] = cq[nt][0] = cq[nt][1] = 0.f;
    }

    #pragma unroll
    for (int mt = 0; mt < 2; mt++) {
        int r0 = erow + mt * 16;
        #pragma unroll
        for (int nt = 0; nt < 8; nt++) {
            int col = ecol0 + nt * 8;
            float b0 = __ldg(bias + col), b1 = __ldg(bias + col + 1);
            float v0 = acc[mt][nt][0] + b0;
            float v1 = acc[mt][nt][1] + b1;
            float v2 = acc[mt][nt][2] + b0;
            float v3 = acc[mt][nt][3] + b1;
            if (!P2) {
                if (r0 < Mreal) {
                    cs[nt][0] += v0; cq[nt][0] += v0 * v0;
                    cs[nt][1] += v1; cq[nt][1] += v1 * v1;
                }
                if (r0 + 8 < Mreal) {
                    cs[nt][0] += v2; cq[nt][0] += v2 * v2;
                    cs[nt][1] += v3; cq[nt][1] += v3 * v3;
                }
            }
            if (P2) {
                v0 = fmaxf(v0, 0.f); v1 = fmaxf(v1, 0.f);
                v2 = fmaxf(v2, 0.f); v3 = fmaxf(v3, 0.f);
            }
            *reinterpret_cast<float2*>(&C[(size_t)r0 * HD + col])
                = make_float2(v0, v1);
            *reinterpret_cast<float2*>(&C[(size_t)(r0 + 8) * HD + col])
                = make_float2(v2, v3);
        }
    }

    if (!P2) {
        float* st = &g_stats[layer * 2 * HD];
        #pragma unroll
        for (int nt = 0; nt < 8; nt++) {
            #pragma unroll
            for (int j = 0; j < 2; j++) {
                float s = cs[nt][j], q = cq[nt][j];
                #pragma unroll
                for (int off = 4; off < 32; off <<= 1) {
                    s += __shfl_xor_sync(0xFFFFFFFFu, s, off);
                    q += __shfl_xor_sync(0xFFFFFFFFu, q, off);
                }
                if (lane < 4) {
                    int col = colBase + wn + nt * 8 + lane * 2 + j;
                    atomicAdd(&st[col], s);
                    atomicAdd(&st[HD + col], q);
                }
            }
        }

        // ---- last-block-done BN finalize (replaces bn_finalize launch) ----
        __threadfence();
        __shared__ int sLast;
        if (tid == 0)
            sLast = (atomicAdd(&g_bn_count[layer], 1) == GTILES - 1);
        __syncthreads();
        if (sLast) {
            float inv_n = 1.f / (float)Mreal;
            float m   = st[tid] * inv_n;
            float var = fmaxf(st[HD + tid] * inv_n - m * m, 0.f);
            float a   = gamma[tid] * rsqrtf(var + BN_EPS);
            g_bna[tid] = a;
            g_bnb[tid] = beta[tid] - a * m;
        }
    }
}

// ------------------------ pool + head MLP ----------------------------------
__global__ void __launch_bounds__(256) pool_head_kernel(
    const int* __restrict__ batch, int n,
    const float* __restrict__ W1, const float* __restrict__ b1,
    const float* __restrict__ W2, const float* __restrict__ b2,
    float* __restrict__ out, int OUTC)
{
    int g = blockIdx.x;
    int tid = threadIdx.x;
    __shared__ float acc[HD];
    __shared__ float hid[HD];

    int lo = 0, hi = n;
    while (lo < hi) { int mid = (lo + hi) >> 1; if (batch[mid] < g) lo = mid + 1; else hi = mid; }
    int s = lo;
    hi = n;
    while (lo < hi) { int mid = (lo + hi) >> 1; if (batch[mid] < g + 1) lo = mid + 1; else hi = mid; }
    int e = lo;

    float a = 0.f;
    for (int r = s; r < e; r++) a += g_h[(size_t)r * HD + tid];
    acc[tid] = a;
    __syncthreads();

    float v = b1[tid];
    #pragma unroll 8
    for (int k = 0; k < HD; k++) v = fmaf(acc[k], W1[k * HD + tid], v);
    hid[tid] = fmaxf(v, 0.f);
    __syncthreads();

    if (tid < OUTC) {
        float o = b2[tid];
        #pragma unroll 8
        for (int k = 0; k < HD; k++) o = fmaf(hid[k], W2[k * OUTC + tid], o);
        out[g * OUTC + tid] = o;
    }
}

// ------------------------------- launch ------------------------------------
extern "C" void kernel_launch(void* const* d_in, const int* in_sizes, int n_in,
                              void* d_out, int out_size) {
    const float* x      = (const float*)d_in[0];
    const int*   ei     = (const int*)  d_in[1];
    const int*   batch  = (const int*)  d_in[2];
    const float* c0_W1  = (const float*)d_in[4];
    const float* c0_b1  = (const float*)d_in[5];
    const float* c0_g   = (const float*)d_in[6];
    const float* c0_be  = (const float*)d_in[7];
    const float* c0_W2  = (const float*)d_in[8];
    const float* c0_b2  = (const float*)d_in[9];
    const float* cs_W1  = (const float*)d_in[10];
    const float* cs_b1  = (const float*)d_in[11];
    const float* cs_g   = (const float*)d_in[12];
    const float* cs_be  = (const float*)d_in[13];
    const float* cs_W2  = (const float*)d_in[14];
    const float* cs_b2  = (const float*)d_in[15];
    const float* mlp_W1 = (const float*)d_in[16];
    const float* mlp_b1 = (const float*)d_in[17];
    const float* mlp_W2 = (const float*)d_in[18];
    const float* mlp_b2 = (const float*)d_in[19];

    const int N    = in_sizes[2];
    const int E    = in_sizes[1] / 2;
    const int OUTC = 10;
    const int G    = out_size / OUTC;
    float* out = (float*)d_out;

    cudaFuncSetAttribute(gemm_mma<128, false>,
                         cudaFuncAttributeMaxDynamicSharedMemorySize, S_TOT);
    cudaFuncSetAttribute(gemm_mma<256, false>,
                         cudaFuncAttributeMaxDynamicSharedMemorySize, S_TOT);
    cudaFuncSetAttribute(gemm_mma<256, true>,
                         cudaFuncAttributeMaxDynamicSharedMemorySize, S_TOT);

    const dim3 gemmGrid(M_PAD / 128, 2);   // 391 x 2

    // CSR build
    zero_kernel<<<(NN + 255) / 256, 256>>>();
    hist_kernel<<<(E + 255) / 256, 256>>>(ei, E);
    scan_kernel<<<1, 1024>>>(N);
    scatter_kernel<<<(E + 255) / 256, 256>>>(ei, E);

    // weight prep (single kernel, all 6 slots)
    {
        const int TOTAL = 128 * HD + 5 * HD * HD;
        wprep_all_kernel<<<(TOTAL + 255) / 256, 256>>>(
            c0_W1, c0_W2, cs_W1, cs_W2,
            cs_W1 + (size_t)HD * HD, cs_W2 + (size_t)HD * HD);
    }

    const int aggBlocks128 = M_PAD / 8;          // 1 warp/node
    const int aggBlocks256 = M_PAD * 2 / 8;      // 2 warps/node

    // ---- conv layer 0 (C_IN=128) ----
    agg_kernel<128, true><<<aggBlocks128, 256>>>(x);
    gemm_mma<128, false><<<gemmGrid, 256, S_TOT>>>(0, c0_b1, N, 0,
                                                   c0_g, c0_be);
    gemm_mma<256, true><<<gemmGrid, 256, S_TOT>>>(1, c0_b2, N, 0,
                                                  nullptr, nullptr);

    // ---- conv layers 1..2 ----
    for (int l = 0; l < 2; l++) {
        agg_kernel<256, false><<<aggBlocks256, 256>>>(nullptr);
        gemm_mma<256, false><<<gemmGrid, 256, S_TOT>>>(2 + l * 2,
                                                       cs_b1 + l * HD, N, l + 1,
                                                       cs_g + l * HD,
                                                       cs_be + l * HD);
        gemm_mma<256, true><<<gemmGrid, 256, S_TOT>>>(3 + l * 2,
                                                      cs_b2 + l * HD, N, l + 1,
                                                      nullptr, nullptr);
    }

    // ---- pool + head ----
    pool_head_kernel<<<G, 256>>>(batch, N, mlp_W1, mlp_b1, mlp_W2, mlp_b2,
                                 out, OUTC);
}

// round 16
// speedup vs baseline: 1.0450x; 1.0450x over previous
#include <cuda_runtime.h>
#include <cuda_bf16.h>
#include <cstdint>

// ---------------------------------------------------------------------------
// GIN forward on GB300 — FINAL: R8 verbatim (validated 718.8us, reproduced
// to +-0.1us in R13). Five single-change perturbations of the GEMM kernel
// (R9 pipeline reorder, R11 prologue BN, R12 persistent, R14 streams,
// R15 tail BN) each regressed 30-50us — the mainloop sits on the 128-reg
// occupancy-2 knife edge and any source change tips it. Components are at
// their floors: agg = L2-BW floor (~190us), GEMMs = mma.sync issue floor
// (~380us; tcgen05 unavailable on the sm_100 target).
//  GEMM core:
//   - __launch_bounds__(256,2); B fragments loaded per-np (low reg pressure)
//   - 64B-swizzled bf16 tiles (conflict-free, no padding)
//   - pipelined loop: prefetch 2 ahead (B 3-stage), transform(c+1) after
//     mma(c), one __syncthreads per chunk, wait_group<=1
//   - A loaded fp32, BN+ReLU fused into the in-SMEM transform (GEMM2);
//     BN stats shuffle-reduced in GEMM1's epilogue.
// GEMM: D = Ahi@Bhi + Ahi@Blo + Alo@Bhi (Markidis), fp32 accum, mma.m16n8k16.
// ---------------------------------------------------------------------------

#define NN      50000
#define M_PAD   50048            // 391 * 128
#define HD      256
#define EMAX    800000
#define BN_EPS  1e-5f

// ------------------------- scratch (device globals) ------------------------
__device__ int   g_deg[NN];
__device__ int   g_cursor[NN];
__device__ int   g_rowptr[NN + 1];
__device__ int   g_adj[EMAX];
__device__ float g_m[(size_t)M_PAD * HD];       // aggregated (fp32)
__device__ float g_t[(size_t)M_PAD * HD];       // GEMM1 out (pre-BN)
__device__ float g_h[(size_t)M_PAD * HD];       // layer output
__device__ __nv_bfloat16 g_wthi[6 * HD * HD];   // weights [n,k] bf16 hi
__device__ __nv_bfloat16 g_wtlo[6 * HD * HD];   // bf16 lo
__device__ float g_stats[3 * 2 * HD];
__device__ __align__(16) float g_bna[HD];
__device__ __align__(16) float g_bnb[HD];

// ------------------------------ PTX helpers --------------------------------
__device__ __forceinline__ uint32_t smem_u32(const void* p) {
    uint32_t a;
    asm("{ .reg .u64 t; cvta.to.shared.u64 t, %1; cvt.u32.u64 %0, t; }"
        : "=r"(a) : "l"(p));
    return a;
}
#define CP_ASYNC16(dst, src) \
    asm volatile("cp.async.cg.shared.global [%0], [%1], 16;" \
                 :: "r"(dst), "l"(src) : "memory")
#define CP_COMMIT()  asm volatile("cp.async.commit_group;" ::: "memory")
#define CP_WAIT0()   asm volatile("cp.async.wait_group 0;" ::: "memory")
#define CP_WAIT1()   asm volatile("cp.async.wait_group 1;" ::: "memory")

__device__ __forceinline__ void ldm_x4(uint32_t* r, uint32_t addr) {
    asm volatile("ldmatrix.sync.aligned.m8n8.x4.shared.b16 {%0,%1,%2,%3}, [%4];"
                 : "=r"(r[0]), "=r"(r[1]), "=r"(r[2]), "=r"(r[3]) : "r"(addr));
}
__device__ __forceinline__ void mma_bf16(float* d, const uint32_t* a,
                                         const uint32_t* b) {
    asm volatile(
        "mma.sync.aligned.m16n8k16.row.col.f32.bf16.bf16.f32 "
        "{%0,%1,%2,%3}, {%4,%5,%6,%7}, {%8,%9}, {%0,%1,%2,%3};"
        : "+f"(d[0]), "+f"(d[1]), "+f"(d[2]), "+f"(d[3])
        : "r"(a[0]), "r"(a[1]), "r"(a[2]), "r"(a[3]), "r"(b[0]), "r"(b[1]));
}

// 64B-row swizzle: 16B unit u16 (0..3) XOR'd with ((row>>1)&3).
// Conflict-free for ldmatrix (8 consecutive rows hit 8 distinct 16B phases).
__device__ __forceinline__ uint32_t swz64(int row, int u16) {
    return (uint32_t)(row * 64 + (((u16) ^ ((row >> 1) & 3)) << 4));
}

// ------------------------------ zero init ----------------------------------
__global__ void zero_kernel() {
    int i = blockIdx.x * blockDim.x + threadIdx.x;
    if (i < NN) g_deg[i] = 0;
    if (i < 3 * 2 * HD) g_stats[i] = 0.f;
}

// ------------------------------ CSR build ----------------------------------
__global__ void hist_kernel(const int* __restrict__ ei, int E) {
    int i = blockIdx.x * blockDim.x + threadIdx.x;
    if (i < E) atomicAdd(&g_deg[ei[E + i]], 1);
}

__global__ void scan_kernel(int n) {
    __shared__ int wsum[32];
    __shared__ int carry;
    int tid = threadIdx.x, lane = tid & 31, wid = tid >> 5;
    if (tid == 0) carry = 0;
    __syncthreads();
    for (int base = 0; base < n; base += 1024) {
        int v = (base + tid < n) ? g_deg[base + tid] : 0;
        int x = v;
        #pragma unroll
        for (int off = 1; off < 32; off <<= 1) {
            int t = __shfl_up_sync(0xFFFFFFFFu, x, off);
            if (lane >= off) x += t;
        }
        if (lane == 31) wsum[wid] = x;
        __syncthreads();
        if (wid == 0) {
            int s = wsum[lane];
            #pragma unroll
            for (int off = 1; off < 32; off <<= 1) {
                int t = __shfl_up_sync(0xFFFFFFFFu, s, off);
                if (lane >= off) s += t;
            }
            wsum[lane] = s;
        }
        __syncthreads();
        int excl = carry + (wid ? wsum[wid - 1] : 0) + x - v;
        if (base + tid < n) {
            g_rowptr[base + tid] = excl;
            g_cursor[base + tid] = excl;
        }
        int total = wsum[31];
        __syncthreads();
        if (tid == 0) carry += total;
        __syncthreads();
    }
    if (tid == 0) g_rowptr[n] = carry;
}

__global__ void scatter_kernel(const int* __restrict__ ei, int E) {
    int i = blockIdx.x * blockDim.x + threadIdx.x;
    if (i < E) {
        int dst = ei[E + i];
        int pos = atomicAdd(&g_cursor[dst], 1);
        g_adj[pos] = ei[i];
    }
}

// --------------------------- pull aggregation ------------------------------
template <int K, bool FIRST>
__global__ void __launch_bounds__(256) agg_kernel(const float* __restrict__ hin) {
    constexpr int WPN = K / 128;
    constexpr int CV4 = K / 4;
    int gw   = (blockIdx.x * blockDim.x + threadIdx.x) >> 5;
    int lane = threadIdx.x & 31;
    int node = gw / WPN;
    int half = gw % WPN;
    if (node >= M_PAD) return;

    size_t vidx = (size_t)node * CV4 + half * 32 + lane;
    float4* m4 = reinterpret_cast<float4*>(g_m);

    if (node >= NN) {
        m4[vidx] = make_float4(0.f, 0.f, 0.f, 0.f);
        return;
    }

    const float*  h  = FIRST ? hin : (const float*)g_h;
    const float4* h4 = reinterpret_cast<const float4*>(h);
    const int co = half * 32 + lane;

    float4 acc = h4[vidx];

    int s = g_rowptr[node], e = g_rowptr[node + 1];
    int j = s;
    for (; j + 8 <= e; j += 8) {
        int idx[8];
        #pragma unroll
        for (int u = 0; u < 8; u++) idx[u] = __ldg(&g_adj[j + u]);
        float4 v[8];
        #pragma unroll
        for (int u = 0; u < 8; u++) v[u] = __ldg(&h4[(size_t)idx[u] * CV4 + co]);
        #pragma unroll
        for (int u = 0; u < 8; u++) {
            acc.x += v[u].x; acc.y += v[u].y; acc.z += v[u].z; acc.w += v[u].w;
        }
    }
    for (; j < e; j++) {
        int src = __ldg(&g_adj[j]);
        float4 v = __ldg(&h4[(size_t)src * CV4 + co]);
        acc.x += v.x; acc.y += v.y; acc.z += v.z; acc.w += v.w;
    }
    m4[vidx] = acc;
}

// --------------------------- weight prep -----------------------------------
__global__ void wprep_all_kernel(const float* __restrict__ w0,
                                 const float* __restrict__ w1,
                                 const float* __restrict__ w2,
                                 const float* __restrict__ w3,
                                 const float* __restrict__ w4,
                                 const float* __restrict__ w5) {
    int idx = blockIdx.x * blockDim.x + threadIdx.x;
    const int S0 = 128 * HD;
    const int TOTAL = S0 + 5 * HD * HD;
    if (idx >= TOTAL) return;
    const float* src;
    int slot, K, li;
    if (idx < S0) { slot = 0; K = 128; li = idx; src = w0; }
    else {
        int r = idx - S0;
        slot = 1 + r / (HD * HD);
        li = r % (HD * HD);
        K = 256;
        src = (slot == 1) ? w1 : (slot == 2) ? w2 : (slot == 3) ? w3
            : (slot == 4) ? w4 : w5;
    }
    int k = li / HD, n = li % HD;
    float v = src[li];
    __nv_bfloat16 hi = __float2bfloat16(v);
    float r2 = v - __bfloat162float(hi);
    size_t o = (size_t)slot * HD * HD + (size_t)n * K + k;
    g_wthi[o] = hi;
    g_wtlo[o] = __float2bfloat16(r2);
}

// -------------------------- mma.sync GEMM ----------------------------------
// BM=128, BN=128, BK=32, 256 threads, 2 CTAs/SM enforced.
// SMEM: A32 fp32 2 stages (16KB ea) | A hi/lo 2 stages (8KB ea, swizzled) |
//       B hi/lo 3 stages (8KB ea, swizzled).  Total 114688 -> occ 2.
#define AS32   16384
#define ATS    8192
#define BTS    8192
#define S_A32  0
#define S_AHI  32768
#define S_ALO  49152
#define S_BHI  65536
#define S_BLO  90112
#define S_TOT  114688

template <int K, bool P2>
__global__ void __launch_bounds__(256, 2) gemm_mma(int wslot,
                                                   const float* __restrict__ bias,
                                                   int Mreal, int layer) {
    constexpr int CHUNKS = K / 32;
    extern __shared__ char smem[];
    const uint32_t sb = smem_u32(smem);

    const int tid  = threadIdx.x;
    const int wid  = tid >> 5;
    const int lane = tid & 31;
    const int rowBase = blockIdx.x * 128;
    const int colBase = blockIdx.y * 128;
    const int wm = (wid >> 1) * 32;
    const int wn = (wid & 1) * 64;

    const __nv_bfloat16* Whi = g_wthi + (size_t)wslot * HD * HD;
    const __nv_bfloat16* Wlo = g_wtlo + (size_t)wslot * HD * HD;
    const float* A = P2 ? (const float*)g_t : (const float*)g_m;
    float*       C = P2 ? g_h : g_t;

    // ---- prefetch chunk c: A fp32 stage c&1, B hi/lo stage c%3 ----
    auto prefetch = [&](int c) {
        const uint32_t as = (c & 1) * AS32;
        #pragma unroll
        for (int i = 0; i < 4; i++) {
            int u = tid + i * 256;
            int r = u >> 3, q = u & 7;
            CP_ASYNC16(sb + S_A32 + as + r * 128 + q * 16,
                       (const void*)&A[(size_t)(rowBase + r) * K + c * 32 + q * 4]);
        }
        const uint32_t bs = (c % 3) * BTS;
        #pragma unroll
        for (int i = 0; i < 2; i++) {
            int u = tid * 2 + i;
            int r = u >> 2, c8 = u & 3;
            uint32_t sof = bs + swz64(r, c8);
            size_t gb = (size_t)(colBase + r) * K + c * 32 + c8 * 8;
            CP_ASYNC16(sb + S_BHI + sof, (const void*)&Whi[gb]);
            CP_ASYNC16(sb + S_BLO + sof, (const void*)&Wlo[gb]);
        }
        CP_COMMIT();
    };

    // ---- transform chunk c: fp32 -> (BN+ReLU if P2) -> bf16 hi/lo tiles ----
    auto transform = [&](int c) {
        const uint32_t as  = (c & 1) * AS32;
        const uint32_t ahs = (c & 1) * ATS;
        #pragma unroll
        for (int i = 0; i < 4; i++) {
            int u = tid + i * 256;
            int r = u >> 3, q = u & 7;
            float4 v = *reinterpret_cast<const float4*>(
                smem + S_A32 + as + r * 128 + q * 16);
            if (P2) {
                int col = c * 32 + q * 4;
                float4 a4 = *reinterpret_cast<const float4*>(&g_bna[col]);
                float4 b4 = *reinterpret_cast<const float4*>(&g_bnb[col]);
                v.x = fmaxf(fmaf(a4.x, v.x, b4.x), 0.f);
                v.y = fmaxf(fmaf(a4.y, v.y, b4.y), 0.f);
                v.z = fmaxf(fmaf(a4.z, v.z, b4.z), 0.f);
                v.w = fmaxf(fmaf(a4.w, v.w, b4.w), 0.f);
            }
            __nv_bfloat16 h0 = __float2bfloat16(v.x);
            __nv_bfloat16 h1 = __float2bfloat16(v.y);
            __nv_bfloat16 h2 = __float2bfloat16(v.z);
            __nv_bfloat16 h3 = __float2bfloat16(v.w);
            __nv_bfloat162 ph0 = __halves2bfloat162(h0, h1);
            __nv_bfloat162 ph1 = __halves2bfloat162(h2, h3);
            __nv_bfloat162 pl0 = __halves2bfloat162(
                __float2bfloat16(v.x - __bfloat162float(h0)),
                __float2bfloat16(v.y - __bfloat162float(h1)));
            __nv_bfloat162 pl1 = __halves2bfloat162(
                __float2bfloat16(v.z - __bfloat162float(h2)),
                __float2bfloat16(v.w - __bfloat162float(h3)));
            uint2 uh, ul;
            uh.x = *reinterpret_cast<uint32_t*>(&ph0);
            uh.y = *reinterpret_cast<uint32_t*>(&ph1);
            ul.x = *reinterpret_cast<uint32_t*>(&pl0);
            ul.y = *reinterpret_cast<uint32_t*>(&pl1);
            uint32_t off = ahs + swz64(r, q >> 1) + (q & 1) * 8;
            *reinterpret_cast<uint2*>(smem + S_AHI + off) = uh;
            *reinterpret_cast<uint2*>(smem + S_ALO + off) = ul;
        }
    };

    float acc[2][8][4];
    #pragma unroll
    for (int mt = 0; mt < 2; mt++)
        #pragma unroll
        for (int nt = 0; nt < 8; nt++)
            #pragma unroll
            for (int j = 0; j < 4; j++) acc[mt][nt][j] = 0.f;

    const int arow = (lane & 7) + ((lane >> 3) & 1) * 8;
    const int akh  = (lane >> 4) * 8;
    const int brow = (lane & 7) + ((lane >> 4) & 1) * 8;
    const int bkh  = ((lane >> 3) & 1) * 8;

    // ---- preamble ----
    prefetch(0);
    prefetch(1);
    CP_WAIT1();                 // cp(0) done, cp(1) in flight
    transform(0);
    __syncthreads();

    // ---- pipelined mainloop: one sync per chunk ----
    #pragma unroll 1
    for (int c = 0; c < CHUNKS; c++) {
        if (c + 2 < CHUNKS) prefetch(c + 2);

        const uint32_t ahs = (c & 1) * ATS;
        const uint32_t bss = (c % 3) * BTS;
        #pragma unroll
        for (int kk = 0; kk < 32; kk += 16) {
            const int u16a = (kk + akh) >> 3;
            uint32_t ah[2][4], al[2][4];
            #pragma unroll
            for (int mt = 0; mt < 2; mt++) {
                uint32_t sw = swz64(wm + mt * 16 + arow, u16a);
                ldm_x4(ah[mt], sb + S_AHI + ahs + sw);
                ldm_x4(al[mt], sb + S_ALO + ahs + sw);
            }
            const int u16b = (kk + bkh) >> 3;
            #pragma unroll
            for (int np = 0; np < 4; np++) {
                uint32_t sw = swz64(wn + np * 16 + brow, u16b);
                uint32_t th[4], tl[4];
                ldm_x4(th, sb + S_BHI + bss + sw);
                ldm_x4(tl, sb + S_BLO + bss + sw);
                #pragma unroll
                for (int mt = 0; mt < 2; mt++) {
                    mma_bf16(acc[mt][np * 2],     ah[mt], th);
                    mma_bf16(acc[mt][np * 2],     ah[mt], tl);
                    mma_bf16(acc[mt][np * 2],     al[mt], th);
                    mma_bf16(acc[mt][np * 2 + 1], ah[mt], th + 2);
                    mma_bf16(acc[mt][np * 2 + 1], ah[mt], tl + 2);
                    mma_bf16(acc[mt][np * 2 + 1], al[mt], th + 2);
                }
            }
        }

        if (c + 1 < CHUNKS) {
            if (c + 2 < CHUNKS) { CP_WAIT1(); } else { CP_WAIT0(); }
            transform(c + 1);
        }
        __syncthreads();
    }

    // -------- epilogue --------
    const int erow  = rowBase + wm + (lane >> 2);
    const int ecol0 = colBase + wn + (lane & 3) * 2;

    float cs[8][2], cq[8][2];
    if (!P2) {
        #pragma unroll
        for (int nt = 0; nt < 8; nt++)
            cs[nt][0] = cs[nt][1] = cq[nt][0] = cq[nt][1] = 0.f;
    }

    #pragma unroll
    for (int mt = 0; mt < 2; mt++) {
        int r0 = erow + mt * 16;
        #pragma unroll
        for (int nt = 0; nt < 8; nt++) {
            int col = ecol0 + nt * 8;
            float b0 = __ldg(bias + col), b1 = __ldg(bias + col + 1);
            float v0 = acc[mt][nt][0] + b0;
            float v1 = acc[mt][nt][1] + b1;
            float v2 = acc[mt][nt][2] + b0;
            float v3 = acc[mt][nt][3] + b1;
            if (!P2) {
                if (r0 < Mreal) {
                    cs[nt][0] += v0; cq[nt][0] += v0 * v0;
                    cs[nt][1] += v1; cq[nt][1] += v1 * v1;
                }
                if (r0 + 8 < Mreal) {
                    cs[nt][0] += v2; cq[nt][0] += v2 * v2;
                    cs[nt][1] += v3; cq[nt][1] += v3 * v3;
                }
            }
            if (P2) {
                v0 = fmaxf(v0, 0.f); v1 = fmaxf(v1, 0.f);
                v2 = fmaxf(v2, 0.f); v3 = fmaxf(v3, 0.f);
            }
            *reinterpret_cast<float2*>(&C[(size_t)r0 * HD + col])
                = make_float2(v0, v1);
            *reinterpret_cast<float2*>(&C[(size_t)(r0 + 8) * HD + col])
                = make_float2(v2, v3);
        }
    }

    if (!P2) {
        float* st = &g_stats[layer * 2 * HD];
        #pragma unroll
        for (int nt = 0; nt < 8; nt++) {
            #pragma unroll
            for (int j = 0; j < 2; j++) {
                float s = cs[nt][j], q = cq[nt][j];
                #pragma unroll
                for (int off = 4; off < 32; off <<= 1) {
                    s += __shfl_xor_sync(0xFFFFFFFFu, s, off);
                    q += __shfl_xor_sync(0xFFFFFFFFu, q, off);
                }
                if (lane < 4) {
                    int col = colBase + wn + nt * 8 + lane * 2 + j;
                    atomicAdd(&st[col], s);
                    atomicAdd(&st[HD + col], q);
                }
            }
        }
    }
}

// --------------------------- BN finalize -----------------------------------
__global__ void bn_finalize_kernel(const float* __restrict__ gamma,
                                   const float* __restrict__ beta,
                                   int n, int layer) {
    int c = threadIdx.x;
    const float* stats = &g_stats[layer * 2 * HD];
    float inv_n = 1.f / (float)n;
    float m   = stats[c] * inv_n;
    float var = fmaxf(stats[HD + c] * inv_n - m * m, 0.f);
    float a   = gamma[c] * rsqrtf(var + BN_EPS);
    g_bna[c] = a;
    g_bnb[c] = beta[c] - a * m;
}

// ------------------------ pool + head MLP ----------------------------------
__global__ void __launch_bounds__(256) pool_head_kernel(
    const int* __restrict__ batch, int n,
    const float* __restrict__ W1, const float* __restrict__ b1,
    const float* __restrict__ W2, const float* __restrict__ b2,
    float* __restrict__ out, int OUTC)
{
    int g = blockIdx.x;
    int tid = threadIdx.x;
    __shared__ float acc[HD];
    __shared__ float hid[HD];

    int lo = 0, hi = n;
    while (lo < hi) { int mid = (lo + hi) >> 1; if (batch[mid] < g) lo = mid + 1; else hi = mid; }
    int s = lo;
    hi = n;
    while (lo < hi) { int mid = (lo + hi) >> 1; if (batch[mid] < g + 1) lo = mid + 1; else hi = mid; }
    int e = lo;

    float a = 0.f;
    for (int r = s; r < e; r++) a += g_h[(size_t)r * HD + tid];
    acc[tid] = a;
    __syncthreads();

    float v = b1[tid];
    #pragma unroll 8
    for (int k = 0; k < HD; k++) v = fmaf(acc[k], W1[k * HD + tid], v);
    hid[tid] = fmaxf(v, 0.f);
    __syncthreads();

    if (tid < OUTC) {
        float o = b2[tid];
        #pragma unroll 8
        for (int k = 0; k < HD; k++) o = fmaf(hid[k], W2[k * OUTC + tid], o);
        out[g * OUTC + tid] = o;
    }
}

// ------------------------------- launch ------------------------------------
extern "C" void kernel_launch(void* const* d_in, const int* in_sizes, int n_in,
                              void* d_out, int out_size) {
    const float* x      = (const float*)d_in[0];
    const int*   ei     = (const int*)  d_in[1];
    const int*   batch  = (const int*)  d_in[2];
    const float* c0_W1  = (const float*)d_in[4];
    const float* c0_b1  = (const float*)d_in[5];
    const float* c0_g   = (const float*)d_in[6];
    const float* c0_be  = (const float*)d_in[7];
    const float* c0_W2  = (const float*)d_in[8];
    const float* c0_b2  = (const float*)d_in[9];
    const float* cs_W1  = (const float*)d_in[10];
    const float* cs_b1  = (const float*)d_in[11];
    const float* cs_g   = (const float*)d_in[12];
    const float* cs_be  = (const float*)d_in[13];
    const float* cs_W2  = (const float*)d_in[14];
    const float* cs_b2  = (const float*)d_in[15];
    const float* mlp_W1 = (const float*)d_in[16];
    const float* mlp_b1 = (const float*)d_in[17];
    const float* mlp_W2 = (const float*)d_in[18];
    const float* mlp_b2 = (const float*)d_in[19];

    const int N    = in_sizes[2];
    const int E    = in_sizes[1] / 2;
    const int OUTC = 10;
    const int G    = out_size / OUTC;
    float* out = (float*)d_out;

    cudaFuncSetAttribute(gemm_mma<128, false>,
                         cudaFuncAttributeMaxDynamicSharedMemorySize, S_TOT);
    cudaFuncSetAttribute(gemm_mma<256, false>,
                         cudaFuncAttributeMaxDynamicSharedMemorySize, S_TOT);
    cudaFuncSetAttribute(gemm_mma<256, true>,
                         cudaFuncAttributeMaxDynamicSharedMemorySize, S_TOT);

    const dim3 gemmGrid(M_PAD / 128, 2);   // 391 x 2

    // CSR build
    zero_kernel<<<(NN + 255) / 256, 256>>>();
    hist_kernel<<<(E + 255) / 256, 256>>>(ei, E);
    scan_kernel<<<1, 1024>>>(N);
    scatter_kernel<<<(E + 255) / 256, 256>>>(ei, E);

    // weight prep (single kernel, all 6 slots)
    {
        const int TOTAL = 128 * HD + 5 * HD * HD;
        wprep_all_kernel<<<(TOTAL + 255) / 256, 256>>>(
            c0_W1, c0_W2, cs_W1, cs_W2,
            cs_W1 + (size_t)HD * HD, cs_W2 + (size_t)HD * HD);
    }

    const int aggBlocks128 = M_PAD / 8;          // 1 warp/node
    const int aggBlocks256 = M_PAD * 2 / 8;      // 2 warps/node

    // ---- conv layer 0 (C_IN=128) ----
    agg_kernel<128, true><<<aggBlocks128, 256>>>(x);
    gemm_mma<128, false><<<gemmGrid, 256, S_TOT>>>(0, c0_b1, N, 0);
    bn_finalize_kernel<<<1, HD>>>(c0_g, c0_be, N, 0);
    gemm_mma<256, true><<<gemmGrid, 256, S_TOT>>>(1, c0_b2, N, 0);

    // ---- conv layers 1..2 ----
    for (int l = 0; l < 2; l++) {
        agg_kernel<256, false><<<aggBlocks256, 256>>>(nullptr);
        gemm_mma<256, false><<<gemmGrid, 256, S_TOT>>>(2 + l * 2,
                                                       cs_b1 + l * HD, N, l + 1);
        bn_finalize_kernel<<<1, HD>>>(cs_g + l * HD, cs_be + l * HD, N, l + 1);
        gemm_mma<256, true><<<gemmGrid, 256, S_TOT>>>(3 + l * 2,
                                                      cs_b2 + l * HD, N, l + 1);
    }

    // ---- pool + head ----
    pool_head_kernel<<<G, 256>>>(batch, N, mlp_W1, mlp_b1, mlp_W2, mlp_b2,
                                 out, OUTC);
}

// round 17
// speedup vs baseline: 1.0502x; 1.0050x over previous
#include <cuda_runtime.h>
#include <cuda_bf16.h>
#include <cstdint>

// ---------------------------------------------------------------------------
// GIN forward on GB300 — round 17
// R8 verbatim (718.8us, reproduced 3x to +-1us) + ONE change confined to the
// NON-fragile agg kernel: g_m output stores use st.global.cs (evict-first)
// so the write stream does not pollute L2 residency of h (the gather target,
// read ~16x per line). g_m is consumed later by latency-hidden cp.async, so
// its L2 residency is worthless. GEMM source byte-identical.
// GEMM: D = Ahi@Bhi + Ahi@Blo + Alo@Bhi (Markidis), fp32 accum, mma.m16n8k16.
// ---------------------------------------------------------------------------

#define NN      50000
#define M_PAD   50048            // 391 * 128
#define HD      256
#define EMAX    800000
#define BN_EPS  1e-5f

// ------------------------- scratch (device globals) ------------------------
__device__ int   g_deg[NN];
__device__ int   g_cursor[NN];
__device__ int   g_rowptr[NN + 1];
__device__ int   g_adj[EMAX];
__device__ float g_m[(size_t)M_PAD * HD];       // aggregated (fp32)
__device__ float g_t[(size_t)M_PAD * HD];       // GEMM1 out (pre-BN)
__device__ float g_h[(size_t)M_PAD * HD];       // layer output
__device__ __nv_bfloat16 g_wthi[6 * HD * HD];   // weights [n,k] bf16 hi
__device__ __nv_bfloat16 g_wtlo[6 * HD * HD];   // bf16 lo
__device__ float g_stats[3 * 2 * HD];
__device__ __align__(16) float g_bna[HD];
__device__ __align__(16) float g_bnb[HD];

// ------------------------------ PTX helpers --------------------------------
__device__ __forceinline__ uint32_t smem_u32(const void* p) {
    uint32_t a;
    asm("{ .reg .u64 t; cvta.to.shared.u64 t, %1; cvt.u32.u64 %0, t; }"
        : "=r"(a) : "l"(p));
    return a;
}
#define CP_ASYNC16(dst, src) \
    asm volatile("cp.async.cg.shared.global [%0], [%1], 16;" \
                 :: "r"(dst), "l"(src) : "memory")
#define CP_COMMIT()  asm volatile("cp.async.commit_group;" ::: "memory")
#define CP_WAIT0()   asm volatile("cp.async.wait_group 0;" ::: "memory")
#define CP_WAIT1()   asm volatile("cp.async.wait_group 1;" ::: "memory")

__device__ __forceinline__ void ldm_x4(uint32_t* r, uint32_t addr) {
    asm volatile("ldmatrix.sync.aligned.m8n8.x4.shared.b16 {%0,%1,%2,%3}, [%4];"
                 : "=r"(r[0]), "=r"(r[1]), "=r"(r[2]), "=r"(r[3]) : "r"(addr));
}
__device__ __forceinline__ void mma_bf16(float* d, const uint32_t* a,
                                         const uint32_t* b) {
    asm volatile(
        "mma.sync.aligned.m16n8k16.row.col.f32.bf16.bf16.f32 "
        "{%0,%1,%2,%3}, {%4,%5,%6,%7}, {%8,%9}, {%0,%1,%2,%3};"
        : "+f"(d[0]), "+f"(d[1]), "+f"(d[2]), "+f"(d[3])
        : "r"(a[0]), "r"(a[1]), "r"(a[2]), "r"(a[3]), "r"(b[0]), "r"(b[1]));
}

// streaming (evict-first) 128-bit store — keeps the write stream out of L2
__device__ __forceinline__ void stg_cs4(float* p, float4 v) {
    asm volatile("st.global.cs.v4.f32 [%0], {%1, %2, %3, %4};"
                 :: "l"(p), "f"(v.x), "f"(v.y), "f"(v.z), "f"(v.w) : "memory");
}

// 64B-row swizzle: 16B unit u16 (0..3) XOR'd with ((row>>1)&3).
__device__ __forceinline__ uint32_t swz64(int row, int u16) {
    return (uint32_t)(row * 64 + (((u16) ^ ((row >> 1) & 3)) << 4));
}

// ------------------------------ zero init ----------------------------------
__global__ void zero_kernel() {
    int i = blockIdx.x * blockDim.x + threadIdx.x;
    if (i < NN) g_deg[i] = 0;
    if (i < 3 * 2 * HD) g_stats[i] = 0.f;
}

// ------------------------------ CSR build ----------------------------------
__global__ void hist_kernel(const int* __restrict__ ei, int E) {
    int i = blockIdx.x * blockDim.x + threadIdx.x;
    if (i < E) atomicAdd(&g_deg[ei[E + i]], 1);
}

__global__ void scan_kernel(int n) {
    __shared__ int wsum[32];
    __shared__ int carry;
    int tid = threadIdx.x, lane = tid & 31, wid = tid >> 5;
    if (tid == 0) carry = 0;
    __syncthreads();
    for (int base = 0; base < n; base += 1024) {
        int v = (base + tid < n) ? g_deg[base + tid] : 0;
        int x = v;
        #pragma unroll
        for (int off = 1; off < 32; off <<= 1) {
            int t = __shfl_up_sync(0xFFFFFFFFu, x, off);
            if (lane >= off) x += t;
        }
        if (lane == 31) wsum[wid] = x;
        __syncthreads();
        if (wid == 0) {
            int s = wsum[lane];
            #pragma unroll
            for (int off = 1; off < 32; off <<= 1) {
                int t = __shfl_up_sync(0xFFFFFFFFu, s, off);
                if (lane >= off) s += t;
            }
            wsum[lane] = s;
        }
        __syncthreads();
        int excl = carry + (wid ? wsum[wid - 1] : 0) + x - v;
        if (base + tid < n) {
            g_rowptr[base + tid] = excl;
            g_cursor[base + tid] = excl;
        }
        int total = wsum[31];
        __syncthreads();
        if (tid == 0) carry += total;
        __syncthreads();
    }
    if (tid == 0) g_rowptr[n] = carry;
}

__global__ void scatter_kernel(const int* __restrict__ ei, int E) {
    int i = blockIdx.x * blockDim.x + threadIdx.x;
    if (i < E) {
        int dst = ei[E + i];
        int pos = atomicAdd(&g_cursor[dst], 1);
        g_adj[pos] = ei[i];
    }
}

// --------------------------- pull aggregation ------------------------------
template <int K, bool FIRST>
__global__ void __launch_bounds__(256) agg_kernel(const float* __restrict__ hin) {
    constexpr int WPN = K / 128;
    constexpr int CV4 = K / 4;
    int gw   = (blockIdx.x * blockDim.x + threadIdx.x) >> 5;
    int lane = threadIdx.x & 31;
    int node = gw / WPN;
    int half = gw % WPN;
    if (node >= M_PAD) return;

    size_t vidx = (size_t)node * CV4 + half * 32 + lane;
    float4* m4 = reinterpret_cast<float4*>(g_m);

    if (node >= NN) {
        stg_cs4(reinterpret_cast<float*>(&m4[vidx]),
                make_float4(0.f, 0.f, 0.f, 0.f));
        return;
    }

    const float*  h  = FIRST ? hin : (const float*)g_h;
    const float4* h4 = reinterpret_cast<const float4*>(h);
    const int co = half * 32 + lane;

    float4 acc = h4[vidx];

    int s = g_rowptr[node], e = g_rowptr[node + 1];
    int j = s;
    for (; j + 8 <= e; j += 8) {
        int idx[8];
        #pragma unroll
        for (int u = 0; u < 8; u++) idx[u] = __ldg(&g_adj[j + u]);
        float4 v[8];
        #pragma unroll
        for (int u = 0; u < 8; u++) v[u] = __ldg(&h4[(size_t)idx[u] * CV4 + co]);
        #pragma unroll
        for (int u = 0; u < 8; u++) {
            acc.x += v[u].x; acc.y += v[u].y; acc.z += v[u].z; acc.w += v[u].w;
        }
    }
    for (; j < e; j++) {
        int src = __ldg(&g_adj[j]);
        float4 v = __ldg(&h4[(size_t)src * CV4 + co]);
        acc.x += v.x; acc.y += v.y; acc.z += v.z; acc.w += v.w;
    }
    stg_cs4(reinterpret_cast<float*>(&m4[vidx]), acc);
}

// --------------------------- weight prep -----------------------------------
__global__ void wprep_all_kernel(const float* __restrict__ w0,
                                 const float* __restrict__ w1,
                                 const float* __restrict__ w2,
                                 const float* __restrict__ w3,
                                 const float* __restrict__ w4,
                                 const float* __restrict__ w5) {
    int idx = blockIdx.x * blockDim.x + threadIdx.x;
    const int S0 = 128 * HD;
    const int TOTAL = S0 + 5 * HD * HD;
    if (idx >= TOTAL) return;
    const float* src;
    int slot, K, li;
    if (idx < S0) { slot = 0; K = 128; li = idx; src = w0; }
    else {
        int r = idx - S0;
        slot = 1 + r / (HD * HD);
        li = r % (HD * HD);
        K = 256;
        src = (slot == 1) ? w1 : (slot == 2) ? w2 : (slot == 3) ? w3
            : (slot == 4) ? w4 : w5;
    }
    int k = li / HD, n = li % HD;
    float v = src[li];
    __nv_bfloat16 hi = __float2bfloat16(v);
    float r2 = v - __bfloat162float(hi);
    size_t o = (size_t)slot * HD * HD + (size_t)n * K + k;
    g_wthi[o] = hi;
    g_wtlo[o] = __float2bfloat16(r2);
}

// -------------------------- mma.sync GEMM ----------------------------------
// R8 verbatim.
#define AS32   16384
#define ATS    8192
#define BTS    8192
#define S_A32  0
#define S_AHI  32768
#define S_ALO  49152
#define S_BHI  65536
#define S_BLO  90112
#define S_TOT  114688

template <int K, bool P2>
__global__ void __launch_bounds__(256, 2) gemm_mma(int wslot,
                                                   const float* __restrict__ bias,
                                                   int Mreal, int layer) {
    constexpr int CHUNKS = K / 32;
    extern __shared__ char smem[];
    const uint32_t sb = smem_u32(smem);

    const int tid  = threadIdx.x;
    const int wid  = tid >> 5;
    const int lane = tid & 31;
    const int rowBase = blockIdx.x * 128;
    const int colBase = blockIdx.y * 128;
    const int wm = (wid >> 1) * 32;
    const int wn = (wid & 1) * 64;

    const __nv_bfloat16* Whi = g_wthi + (size_t)wslot * HD * HD;
    const __nv_bfloat16* Wlo = g_wtlo + (size_t)wslot * HD * HD;
    const float* A = P2 ? (const float*)g_t : (const float*)g_m;
    float*       C = P2 ? g_h : g_t;

    auto prefetch = [&](int c) {
        const uint32_t as = (c & 1) * AS32;
        #pragma unroll
        for (int i = 0; i < 4; i++) {
            int u = tid + i * 256;
            int r = u >> 3, q = u & 7;
            CP_ASYNC16(sb + S_A32 + as + r * 128 + q * 16,
                       (const void*)&A[(size_t)(rowBase + r) * K + c * 32 + q * 4]);
        }
        const uint32_t bs = (c % 3) * BTS;
        #pragma unroll
        for (int i = 0; i < 2; i++) {
            int u = tid * 2 + i;
            int r = u >> 2, c8 = u & 3;
            uint32_t sof = bs + swz64(r, c8);
            size_t gb = (size_t)(colBase + r) * K + c * 32 + c8 * 8;
            CP_ASYNC16(sb + S_BHI + sof, (const void*)&Whi[gb]);
            CP_ASYNC16(sb + S_BLO + sof, (const void*)&Wlo[gb]);
        }
        CP_COMMIT();
    };

    auto transform = [&](int c) {
        const uint32_t as  = (c & 1) * AS32;
        const uint32_t ahs = (c & 1) * ATS;
        #pragma unroll
        for (int i = 0; i < 4; i++) {
            int u = tid + i * 256;
            int r = u >> 3, q = u & 7;
            float4 v = *reinterpret_cast<const float4*>(
                smem + S_A32 + as + r * 128 + q * 16);
            if (P2) {
                int col = c * 32 + q * 4;
                float4 a4 = *reinterpret_cast<const float4*>(&g_bna[col]);
                float4 b4 = *reinterpret_cast<const float4*>(&g_bnb[col]);
                v.x = fmaxf(fmaf(a4.x, v.x, b4.x), 0.f);
                v.y = fmaxf(fmaf(a4.y, v.y, b4.y), 0.f);
                v.z = fmaxf(fmaf(a4.z, v.z, b4.z), 0.f);
                v.w = fmaxf(fmaf(a4.w, v.w, b4.w), 0.f);
            }
            __nv_bfloat16 h0 = __float2bfloat16(v.x);
            __nv_bfloat16 h1 = __float2bfloat16(v.y);
            __nv_bfloat16 h2 = __float2bfloat16(v.z);
            __nv_bfloat16 h3 = __float2bfloat16(v.w);
            __nv_bfloat162 ph0 = __halves2bfloat162(h0, h1);
            __nv_bfloat162 ph1 = __halves2bfloat162(h2, h3);
            __nv_bfloat162 pl0 = __halves2bfloat162(
                __float2bfloat16(v.x - __bfloat162float(h0)),
                __float2bfloat16(v.y - __bfloat162float(h1)));
            __nv_bfloat162 pl1 = __halves2bfloat162(
                __float2bfloat16(v.z - __bfloat162float(h2)),
                __float2bfloat16(v.w - __bfloat162float(h3)));
            uint2 uh, ul;
            uh.x = *reinterpret_cast<uint32_t*>(&ph0);
            uh.y = *reinterpret_cast<uint32_t*>(&ph1);
            ul.x = *reinterpret_cast<uint32_t*>(&pl0);
            ul.y = *reinterpret_cast<uint32_t*>(&pl1);
            uint32_t off = ahs + swz64(r, q >> 1) + (q & 1) * 8;
            *reinterpret_cast<uint2*>(smem + S_AHI + off) = uh;
            *reinterpret_cast<uint2*>(smem + S_ALO + off) = ul;
        }
    };

    float acc[2][8][4];
    #pragma unroll
    for (int mt = 0; mt < 2; mt++)
        #pragma unroll
        for (int nt = 0; nt < 8; nt++)
            #pragma unroll
            for (int j = 0; j < 4; j++) acc[mt][nt][j] = 0.f;

    const int arow = (lane & 7) + ((lane >> 3) & 1) * 8;
    const int akh  = (lane >> 4) * 8;
    const int brow = (lane & 7) + ((lane >> 4) & 1) * 8;
    const int bkh  = ((lane >> 3) & 1) * 8;

    prefetch(0);
    prefetch(1);
    CP_WAIT1();
    transform(0);
    __syncthreads();

    #pragma unroll 1
    for (int c = 0; c < CHUNKS; c++) {
        if (c + 2 < CHUNKS) prefetch(c + 2);

        const uint32_t ahs = (c & 1) * ATS;
        const uint32_t bss = (c % 3) * BTS;
        #pragma unroll
        for (int kk = 0; kk < 32; kk += 16) {
            const int u16a = (kk + akh) >> 3;
            uint32_t ah[2][4], al[2][4];
            #pragma unroll
            for (int mt = 0; mt < 2; mt++) {
                uint32_t sw = swz64(wm + mt * 16 + arow, u16a);
                ldm_x4(ah[mt], sb + S_AHI + ahs + sw);
                ldm_x4(al[mt], sb + S_ALO + ahs + sw);
            }
            const int u16b = (kk + bkh) >> 3;
            #pragma unroll
            for (int np = 0; np < 4; np++) {
                uint32_t sw = swz64(wn + np * 16 + brow, u16b);
                uint32_t th[4], tl[4];
                ldm_x4(th, sb + S_BHI + bss + sw);
                ldm_x4(tl, sb + S_BLO + bss + sw);
                #pragma unroll
                for (int mt = 0; mt < 2; mt++) {
                    mma_bf16(acc[mt][np * 2],     ah[mt], th);
                    mma_bf16(acc[mt][np * 2],     ah[mt], tl);
                    mma_bf16(acc[mt][np * 2],     al[mt], th);
                    mma_bf16(acc[mt][np * 2 + 1], ah[mt], th + 2);
                    mma_bf16(acc[mt][np * 2 + 1], ah[mt], tl + 2);
                    mma_bf16(acc[mt][np * 2 + 1], al[mt], th + 2);
                }
            }
        }

        if (c + 1 < CHUNKS) {
            if (c + 2 < CHUNKS) { CP_WAIT1(); } else { CP_WAIT0(); }
            transform(c + 1);
        }
        __syncthreads();
    }

    // -------- epilogue --------
    const int erow  = rowBase + wm + (lane >> 2);
    const int ecol0 = colBase + wn + (lane & 3) * 2;

    float cs[8][2], cq[8][2];
    if (!P2) {
        #pragma unroll
        for (int nt = 0; nt < 8; nt++)
            cs[nt][0] = cs[nt][1] = cq[nt][0] = cq[nt][1] = 0.f;
    }

    #pragma unroll
    for (int mt = 0; mt < 2; mt++) {
        int r0 = erow + mt * 16;
        #pragma unroll
        for (int nt = 0; nt < 8; nt++) {
            int col = ecol0 + nt * 8;
            float b0 = __ldg(bias + col), b1 = __ldg(bias + col + 1);
            float v0 = acc[mt][nt][0] + b0;
            float v1 = acc[mt][nt][1] + b1;
            float v2 = acc[mt][nt][2] + b0;
            float v3 = acc[mt][nt][3] + b1;
            if (!P2) {
                if (r0 < Mreal) {
                    cs[nt][0] += v0; cq[nt][0] += v0 * v0;
                    cs[nt][1] += v1; cq[nt][1] += v1 * v1;
                }
                if (r0 + 8 < Mreal) {
                    cs[nt][0] += v2; cq[nt][0] += v2 * v2;
                    cs[nt][1] += v3; cq[nt][1] += v3 * v3;
                }
            }
            if (P2) {
                v0 = fmaxf(v0, 0.f); v1 = fmaxf(v1, 0.f);
                v2 = fmaxf(v2, 0.f); v3 = fmaxf(v3, 0.f);
            }
            *reinterpret_cast<float2*>(&C[(size_t)r0 * HD + col])
                = make_float2(v0, v1);
            *reinterpret_cast<float2*>(&C[(size_t)(r0 + 8) * HD + col])
                = make_float2(v2, v3);
        }
    }

    if (!P2) {
        float* st = &g_stats[layer * 2 * HD];
        #pragma unroll
        for (int nt = 0; nt < 8; nt++) {
            #pragma unroll
            for (int j = 0; j < 2; j++) {
                float s = cs[nt][j], q = cq[nt][j];
                #pragma unroll
                for (int off = 4; off < 32; off <<= 1) {
                    s += __shfl_xor_sync(0xFFFFFFFFu, s, off);
                    q += __shfl_xor_sync(0xFFFFFFFFu, q, off);
                }
                if (lane < 4) {
                    int col = colBase + wn + nt * 8 + lane * 2 + j;
                    atomicAdd(&st[col], s);
                    atomicAdd(&st[HD + col], q);
                }
            }
        }
    }
}

// --------------------------- BN finalize -----------------------------------
__global__ void bn_finalize_kernel(const float* __restrict__ gamma,
                                   const float* __restrict__ beta,
                                   int n, int layer) {
    int c = threadIdx.x;
    const float* stats = &g_stats[layer * 2 * HD];
    float inv_n = 1.f / (float)n;
    float m   = stats[c] * inv_n;
    float var = fmaxf(stats[HD + c] * inv_n - m * m, 0.f);
    float a   = gamma[c] * rsqrtf(var + BN_EPS);
    g_bna[c] = a;
    g_bnb[c] = beta[c] - a * m;
}

// ------------------------ pool + head MLP ----------------------------------
__global__ void __launch_bounds__(256) pool_head_kernel(
    const int* __restrict__ batch, int n,
    const float* __restrict__ W1, const float* __restrict__ b1,
    const float* __restrict__ W2, const float* __restrict__ b2,
    float* __restrict__ out, int OUTC)
{
    int g = blockIdx.x;
    int tid = threadIdx.x;
    __shared__ float acc[HD];
    __shared__ float hid[HD];

    int lo = 0, hi = n;
    while (lo < hi) { int mid = (lo + hi) >> 1; if (batch[mid] < g) lo = mid + 1; else hi = mid; }
    int s = lo;
    hi = n;
    while (lo < hi) { int mid = (lo + hi) >> 1; if (batch[mid] < g + 1) lo = mid + 1; else hi = mid; }
    int e = lo;

    float a = 0.f;
    for (int r = s; r < e; r++) a += g_h[(size_t)r * HD + tid];
    acc[tid] = a;
    __syncthreads();

    float v = b1[tid];
    #pragma unroll 8
    for (int k = 0; k < HD; k++) v = fmaf(acc[k], W1[k * HD + tid], v);
    hid[tid] = fmaxf(v, 0.f);
    __syncthreads();

    if (tid < OUTC) {
        float o = b2[tid];
        #pragma unroll 8
        for (int k = 0; k < HD; k++) o = fmaf(hid[k], W2[k * OUTC + tid], o);
        out[g * OUTC + tid] = o;
    }
}

// ------------------------------- launch ------------------------------------
extern "C" void kernel_launch(void* const* d_in, const int* in_sizes, int n_in,
                              void* d_out, int out_size) {
    const float* x      = (const float*)d_in[0];
    const int*   ei     = (const int*)  d_in[1];
    const int*   batch  = (const int*)  d_in[2];
    const float* c0_W1  = (const float*)d_in[4];
    const float* c0_b1  = (const float*)d_in[5];
    const float* c0_g   = (const float*)d_in[6];
    const float* c0_be  = (const float*)d_in[7];
    const float* c0_W2  = (const float*)d_in[8];
    const float* c0_b2  = (const float*)d_in[9];
    const float* cs_W1  = (const float*)d_in[10];
    const float* cs_b1  = (const float*)d_in[11];
    const float* cs_g   = (const float*)d_in[12];
    const float* cs_be  = (const float*)d_in[13];
    const float* cs_W2  = (const float*)d_in[14];
    const float* cs_b2  = (const float*)d_in[15];
    const float* mlp_W1 = (const float*)d_in[16];
    const float* mlp_b1 = (const float*)d_in[17];
    const float* mlp_W2 = (const float*)d_in[18];
    const float* mlp_b2 = (const float*)d_in[19];

    const int N    = in_sizes[2];
    const int E    = in_sizes[1] / 2;
    const int OUTC = 10;
    const int G    = out_size / OUTC;
    float* out = (float*)d_out;

    cudaFuncSetAttribute(gemm_mma<128, false>,
                         cudaFuncAttributeMaxDynamicSharedMemorySize, S_TOT);
    cudaFuncSetAttribute(gemm_mma<256, false>,
                         cudaFuncAttributeMaxDynamicSharedMemorySize, S_TOT);
    cudaFuncSetAttribute(gemm_mma<256, true>,
                         cudaFuncAttributeMaxDynamicSharedMemorySize, S_TOT);

    const dim3 gemmGrid(M_PAD / 128, 2);   // 391 x 2

    // CSR build
    zero_kernel<<<(NN + 255) / 256, 256>>>();
    hist_kernel<<<(E + 255) / 256, 256>>>(ei, E);
    scan_kernel<<<1, 1024>>>(N);
    scatter_kernel<<<(E + 255) / 256, 256>>>(ei, E);

    // weight prep (single kernel, all 6 slots)
    {
        const int TOTAL = 128 * HD + 5 * HD * HD;
        wprep_all_kernel<<<(TOTAL + 255) / 256, 256>>>(
            c0_W1, c0_W2, cs_W1, cs_W2,
            cs_W1 + (size_t)HD * HD, cs_W2 + (size_t)HD * HD);
    }

    const int aggBlocks128 = M_PAD / 8;          // 1 warp/node
    const int aggBlocks256 = M_PAD * 2 / 8;      // 2 warps/node

    // ---- conv layer 0 (C_IN=128) ----
    agg_kernel<128, true><<<aggBlocks128, 256>>>(x);
    gemm_mma<128, false><<<gemmGrid, 256, S_TOT>>>(0, c0_b1, N, 0);
    bn_finalize_kernel<<<1, HD>>>(c0_g, c0_be, N, 0);
    gemm_mma<256, true><<<gemmGrid, 256, S_TOT>>>(1, c0_b2, N, 0);

    // ---- conv layers 1..2 ----
    for (int l = 0; l < 2; l++) {
        agg_kernel<256, false><<<aggBlocks256, 256>>>(nullptr);
        gemm_mma<256, false><<<gemmGrid, 256, S_TOT>>>(2 + l * 2,
                                                       cs_b1 + l * HD, N, l + 1);
        bn_finalize_kernel<<<1, HD>>>(cs_g + l * HD, cs_be + l * HD, N, l + 1);
        gemm_mma<256, true><<<gemmGrid, 256, S_TOT>>>(3 + l * 2,
                                                      cs_b2 + l * HD, N, l + 1);
    }

    // ---- pool + head ----
    pool_head_kernel<<<G, 256>>>(batch, N, mlp_W1, mlp_b1, mlp_W2, mlp_b2,
                                 out, OUTC);
}